// round 5
// baseline (speedup 1.0000x reference)
#include <cuda_runtime.h>
#include <cuda_bf16.h>
#include <cooperative_groups.h>
#include <math.h>

namespace cg = cooperative_groups;

// Fixed problem dims
#define BB   128
#define TT   255
#define NN   256
#define HH   256
#define FH   1024
#define MM   (BB*TT)          // 32640

// Static device scratch (no allocations allowed)
__device__ float g_alpha[BB * NN];
__device__ float g_P[(size_t)MM * FH];   // 133.7 MB

// ---------------------------------------------------------------------------
// helpers
// ---------------------------------------------------------------------------
__device__ __forceinline__ uint32_t smem_u32(const void* p) {
    uint32_t a;
    asm("{ .reg .u64 t; cvta.to.shared.u64 t, %1; cvt.u32.u64 %0, t; }"
        : "=r"(a) : "l"(p));
    return a;
}
__device__ __forceinline__ void ffma2(unsigned long long& d,
                                      unsigned long long a,
                                      unsigned long long b) {
    asm("fma.rn.f32x2 %0, %1, %2, %0;" : "+l"(d) : "l"(a), "l"(b));
}
__device__ __forceinline__ float pairsum(unsigned long long v) {
    float lo, hi;
    asm("mov.b64 {%0,%1}, %2;" : "=f"(lo), "=f"(hi) : "l"(v));
    return lo + hi;
}
__device__ __forceinline__ void mbar_init(uint32_t mbar, uint32_t count) {
    asm volatile("mbarrier.init.shared.b64 [%0], %1;" :: "r"(mbar), "r"(count)
                 : "memory");
}
__device__ __forceinline__ void mbar_arrive_remote(uint32_t mbar_local,
                                                   uint32_t rank) {
    asm volatile(
        "{\n\t.reg .b32 ra;\n\t"
        "mapa.shared::cluster.u32 ra, %0, %1;\n\t"
        "mbarrier.arrive.release.cluster.shared::cluster.b64 _, [ra];\n\t}"
        :: "r"(mbar_local), "r"(rank) : "memory");
}
__device__ __forceinline__ void mbar_wait_acq(uint32_t mbar, uint32_t parity) {
    uint32_t done;
    asm volatile(
        "{\n\t.reg .pred P;\n\t"
        "mbarrier.try_wait.parity.acquire.cluster.shared::cta.b64 P, [%1], %2;\n\t"
        "selp.b32 %0, 1, 0, P;\n\t}"
        : "=r"(done) : "r"(mbar), "r"(parity) : "memory");
    while (!done) {
        asm volatile(
            "{\n\t.reg .pred P;\n\t"
            "mbarrier.try_wait.parity.acquire.cluster.shared::cta.b64 P, [%1], %2, 0x989680;\n\t"
            "selp.b32 %0, 1, 0, P;\n\t}"
            : "=r"(done) : "r"(mbar), "r"(parity) : "memory");
    }
}
__device__ __forceinline__ float sigf(float x) {
    return __fdividef(1.0f, 1.0f + __expf(-x));
}
__device__ __forceinline__ float tanh_fast(float x) {
    float e = __expf(-2.0f * x);
    return __fdividef(1.0f - e, 1.0f + e);
}

// ---------------------------------------------------------------------------
// K1: alpha[b,n] = softmax_n( b_attn + sum_t X[b,t,n] * Wa[2H+t] )
// (h/c logit terms are constant over n -> vanish under softmax)
// ---------------------------------------------------------------------------
__global__ __launch_bounds__(256) void k_alpha(const float* __restrict__ X,
                                               const float* __restrict__ Wa,
                                               const float* __restrict__ ba) {
    __shared__ float was[TT];
    __shared__ float red[256];
    const int b = blockIdx.x, n = threadIdx.x;
    if (n < TT) was[n] = Wa[2 * HH + n];
    __syncthreads();

    const float* xb = X + (size_t)b * TT * NN + n;
    float acc = ba[0];
#pragma unroll 5
    for (int t = 0; t < TT; ++t) acc = fmaf(xb[(size_t)t * NN], was[t], acc);

    red[n] = acc; __syncthreads();
    for (int s = 128; s > 0; s >>= 1) {
        if (n < s) red[n] = fmaxf(red[n], red[n + s]);
        __syncthreads();
    }
    const float mx = red[0]; __syncthreads();
    const float e = expf(acc - mx);
    red[n] = e; __syncthreads();
    for (int s = 128; s > 0; s >>= 1) {
        if (n < s) red[n] += red[n + s];
        __syncthreads();
    }
    g_alpha[b * NN + n] = e / red[0];
}

// ---------------------------------------------------------------------------
// K2: X_tilde = alpha * X  ->  d_out[0 : MM*NN)
// ---------------------------------------------------------------------------
__global__ __launch_bounds__(256) void k_xtilde(const float* __restrict__ X,
                                                float* __restrict__ out) {
    const int idx = blockIdx.x * 256 + threadIdx.x;          // < MM*NN/4
    const float4 x = ((const float4*)X)[idx];
    const int b   = idx / (TT * NN / 4);
    const int rem = idx - b * (TT * NN / 4);
    const int n4  = rem & (NN / 4 - 1);
    const float4 a = ((const float4*)g_alpha)[b * (NN / 4) + n4];
    float4 o;
    o.x = x.x * a.x; o.y = x.y * a.y; o.z = x.z * a.z; o.w = x.w * a.w;
    ((float4*)out)[idx] = o;
}

// ---------------------------------------------------------------------------
// K3: P = X_tilde @ W_lstm + b_lstm   (M=32640, Ncols=1024, K=256) fp32
// ---------------------------------------------------------------------------
__global__ __launch_bounds__(256) void k_gemm(const float* __restrict__ A,
                                              const float* __restrict__ W,
                                              const float* __restrict__ bias) {
    __shared__ float As[16 * 132];
    __shared__ float Bs[16 * 132];
    const int tx = threadIdx.x & 15;
    const int ty = threadIdx.x >> 4;
    const int m0 = blockIdx.y * 128;
    const int c0 = blockIdx.x * 128;

    float acc[8][8];
#pragma unroll
    for (int i = 0; i < 8; ++i)
#pragma unroll
        for (int j = 0; j < 8; ++j) acc[i][j] = 0.0f;

    for (int kk0 = 0; kk0 < 256; kk0 += 16) {
#pragma unroll
        for (int i = 0; i < 2; ++i) {               // A tile (transposed)
            const int id = threadIdx.x + 256 * i;
            const int q = id & 3, row = id >> 2;
            const float4 v = *(const float4*)(A + (size_t)(m0 + row) * 256 + kk0 + 4 * q);
            As[(4 * q + 0) * 132 + row] = v.x;
            As[(4 * q + 1) * 132 + row] = v.y;
            As[(4 * q + 2) * 132 + row] = v.z;
            As[(4 * q + 3) * 132 + row] = v.w;
        }
#pragma unroll
        for (int i = 0; i < 2; ++i) {               // B tile
            const int id = threadIdx.x + 256 * i;
            const int c4 = id & 31, k = id >> 5;
            *(float4*)(Bs + k * 132 + 4 * c4) =
                *(const float4*)(W + (size_t)(kk0 + k) * 1024 + c0 + 4 * c4);
        }
        __syncthreads();
#pragma unroll
        for (int kk = 0; kk < 16; ++kk) {
            const float4 a0 = *(const float4*)(As + kk * 132 + 4 * ty);
            const float4 a1 = *(const float4*)(As + kk * 132 + 64 + 4 * ty);
            const float4 b0 = *(const float4*)(Bs + kk * 132 + 4 * tx);
            const float4 b1 = *(const float4*)(Bs + kk * 132 + 64 + 4 * tx);
            const float av[8] = {a0.x, a0.y, a0.z, a0.w, a1.x, a1.y, a1.z, a1.w};
            const float bv[8] = {b0.x, b0.y, b0.z, b0.w, b1.x, b1.y, b1.z, b1.w};
#pragma unroll
            for (int i = 0; i < 8; ++i)
#pragma unroll
                for (int j = 0; j < 8; ++j) acc[i][j] = fmaf(av[i], bv[j], acc[i][j]);
        }
        __syncthreads();
    }
#pragma unroll
    for (int i = 0; i < 8; ++i) {
        const int row = (i < 4) ? (4 * ty + i) : (64 + 4 * ty + (i - 4));
        float* p = g_P + (size_t)(m0 + row) * 1024 + c0;
        float4 o0, o1;
        o0.x = acc[i][0] + bias[c0 + 4 * tx + 0];
        o0.y = acc[i][1] + bias[c0 + 4 * tx + 1];
        o0.z = acc[i][2] + bias[c0 + 4 * tx + 2];
        o0.w = acc[i][3] + bias[c0 + 4 * tx + 3];
        o1.x = acc[i][4] + bias[c0 + 64 + 4 * tx + 0];
        o1.y = acc[i][5] + bias[c0 + 64 + 4 * tx + 1];
        o1.z = acc[i][6] + bias[c0 + 64 + 4 * tx + 2];
        o1.w = acc[i][7] + bias[c0 + 64 + 4 * tx + 3];
        *(float4*)(p + 4 * tx) = o0;
        *(float4*)(p + 64 + 4 * tx) = o1;
    }
}

// ---------------------------------------------------------------------------
// K4 v2: LSTM recurrence.
// 16 clusters x 8 CTAs; cluster owns 8 batches; CTA rank owns 32 hidden cols.
// 512 threads: kh = tid>>8 splits k in two halves; warps 8..15 produce
// partial sums into smem, warps 0..7 finish gates + h.
// U slice resident in smem; FFMA2 (f32x2 packed along k); g_P prefetched one
// step ahead; h exchanged via DSMEM stores + double-buffered mbarrier
// (release/acquire at cluster scope) — no cluster.sync in the loop.
// ---------------------------------------------------------------------------
#define PITCH 260
#define UT_FLOATS (128 * PITCH)            // 33280
#define HB_STRIDE (8 * PITCH)              // 2080 floats per buffer
#define HB_OFF    UT_FLOATS
#define RED_OFF   (HB_OFF + 2 * HB_STRIDE)         // 37440
#define MBAR_OFF  (RED_OFF + 2 * 256 * 4)          // 39488 floats (two red bufs)
#define SMEM_FLOATS (MBAR_OFF + 4)                 // 2 x u64 mbarriers
#define SMEM_BYTES  (SMEM_FLOATS * 4)              // 157,968 B

__global__ __launch_bounds__(512, 1) __cluster_dims__(8, 1, 1)
void k_lstm(const float* __restrict__ X, const float* __restrict__ U,
            float* __restrict__ out_enc) {
    extern __shared__ float sm[];
    float* Ut  = sm;
    float* hb  = sm + HB_OFF;
    float* redb = sm + RED_OFF;

    cg::cluster_group cl = cg::this_cluster();
    const int rank = (int)cl.block_rank();           // 0..7
    const int b0   = (blockIdx.x >> 3) * 8;
    const int tid  = threadIdx.x;
    const int kh   = tid >> 8;                       // 0/1 k-half
    const int r    = tid & 255;
    const int lane = tid & 31;
    const int bb   = lane >> 2;                      // batch 0..7
    const int jj   = ((r >> 5) << 2) + (lane & 3);   // hidden col 0..31
    const int jglob = rank * 32 + jj;

    const uint32_t smb = smem_u32(sm);
    const uint32_t mb_base = smb + MBAR_OFF * 4;     // mbar[b] at +8*b

    // Load U slice: Ut[(g*32+jr)*PITCH + k] = U[k*1024 + g*256 + rank*32 + jr]
    for (int idx = tid; idx < 128 * 256; idx += 512) {
        const int k = idx >> 7;
        const int cr = idx & 127;
        const int g = cr >> 5, jr = cr & 31;
        Ut[cr * PITCH + k] = U[(size_t)k * 1024 + g * 256 + rank * 32 + jr];
    }
    // h0 = c0 = X[b,0,0] broadcast across hidden; fill mailbox buffer 0
    for (int idx = tid; idx < 8 * 256; idx += 512) {
        const int b = idx >> 8, k = idx & 255;
        hb[b * PITCH + k] = X[(size_t)(b0 + b) * TT * NN];
    }
    if (tid == 0) {
        mbar_init(mb_base + 0, 64);   // 8 CTAs x 8 producer warps
        mbar_init(mb_base + 8, 64);
    }
    __syncthreads();
    cl.sync();   // once: mbarriers + buffer0 visible cluster-wide

    // per-thread constant pointers
    const ulonglong2* U0 = (const ulonglong2*)(Ut + (0 * 32 + jj) * PITCH + kh * 128);
    const ulonglong2* U1 = (const ulonglong2*)(Ut + (1 * 32 + jj) * PITCH + kh * 128);
    const ulonglong2* U2 = (const ulonglong2*)(Ut + (2 * 32 + jj) * PITCH + kh * 128);
    const ulonglong2* U3 = (const ulonglong2*)(Ut + (3 * 32 + jj) * PITCH + kh * 128);
    const ulonglong2* hcA = (const ulonglong2*)(hb + bb * PITCH + kh * 128);
    const ulonglong2* hcB = (const ulonglong2*)(hb + HB_STRIDE + bb * PITCH + kh * 128);

    const float* Pbase = g_P + ((size_t)(b0 + bb) * TT) * 1024 + jglob;
    float* Obase = out_enc + ((size_t)(b0 + bb) * TT) * HH + jglob;

    float c = X[(size_t)(b0 + bb) * TT * NN];
    float pi = 0.f, pf = 0.f, pg = 0.f, po = 0.f;
    if (kh == 0) { pi = Pbase[0]; pf = Pbase[256]; pg = Pbase[512]; po = Pbase[768]; }

    uint32_t ph0 = 0, ph1 = 0;

    for (int t = 0; t < TT; ++t) {
        const int cb = t & 1;
        if (t > 0) {
            if (cb) { mbar_wait_acq(mb_base + 8, ph1); ph1 ^= 1; }
            else    { mbar_wait_acq(mb_base + 0, ph0); ph0 ^= 1; }
        }
        // prefetch next-step P (warps 0..7 only; warp-uniform predicate)
        float npi = 0.f, npf = 0.f, npg = 0.f, npo = 0.f;
        if (kh == 0 && t + 1 < TT) {
            const float* pr = Pbase + (size_t)(t + 1) * 1024;
            npi = pr[0]; npf = pr[256]; npg = pr[512]; npo = pr[768];
        }

        const ulonglong2* hc = cb ? hcB : hcA;
        unsigned long long ai = 0ull, af = 0ull, ag = 0ull, ao = 0ull;
#pragma unroll
        for (int k = 0; k < 32; ++k) {
            const ulonglong2 hv = hc[k];
            const ulonglong2 v0 = U0[k];
            ffma2(ai, hv.x, v0.x); ffma2(ai, hv.y, v0.y);
            const ulonglong2 v1 = U1[k];
            ffma2(af, hv.x, v1.x); ffma2(af, hv.y, v1.y);
            const ulonglong2 v2 = U2[k];
            ffma2(ag, hv.x, v2.x); ffma2(ag, hv.y, v2.y);
            const ulonglong2 v3 = U3[k];
            ffma2(ao, hv.x, v3.x); ffma2(ao, hv.y, v3.y);
        }
        const float si = pairsum(ai), sf = pairsum(af);
        const float sg = pairsum(ag), so = pairsum(ao);

        float4* red4 = (float4*)(redb + cb * 1024);
        if (kh) red4[r] = make_float4(si, sf, sg, so);
        __syncthreads();

        if (kh == 0) {
            const float4 q = red4[r];
            const float gi = sigf(pi + si + q.x);
            const float gf = sigf(pf + sf + q.y);
            const float gg = tanh_fast(pg + sg + q.z);
            const float go = sigf(po + so + q.w);
            c = gf * c + gi * gg;
            const float h = go * tanh_fast(c);

            Obase[(size_t)t * HH] = h;

            if (t + 1 < TT) {
                float* hn = hb + (1 - cb) * HB_STRIDE;
                const int moff = bb * PITCH + jglob;
#pragma unroll
                for (int r2 = 0; r2 < 8; ++r2) {
                    float* dst = cl.map_shared_rank(hn, r2);
                    dst[moff] = h;
                }
            }
            pi = npi; pf = npf; pg = npg; po = npo;

            if (t + 1 < TT) {
                __syncwarp();
                if (lane == 0) {
                    const uint32_t mb = mb_base + (cb ? 0u : 8u);
#pragma unroll
                    for (int r2 = 0; r2 < 8; ++r2)
                        mbar_arrive_remote(mb, (uint32_t)r2);
                }
            }
        }
    }
}

// ---------------------------------------------------------------------------
extern "C" void kernel_launch(void* const* d_in, const int* in_sizes, int n_in,
                              void* d_out, int out_size) {
    const float* X  = (const float*)d_in[0];
    const float* Wa = (const float*)d_in[1];
    const float* ba = (const float*)d_in[2];
    const float* Wl = (const float*)d_in[3];
    const float* Ul = (const float*)d_in[4];
    const float* bl = (const float*)d_in[5];
    float* out = (float*)d_out;
    float* out_xt  = out;                          // (B,Tm1,N)
    float* out_enc = out + (size_t)MM * NN;        // (B,Tm1,H)

    static int attr_set = 0;
    if (!attr_set) {
        cudaFuncSetAttribute(k_lstm, cudaFuncAttributeMaxDynamicSharedMemorySize,
                             SMEM_BYTES);
        attr_set = 1;
    }

    k_alpha<<<BB, 256>>>(X, Wa, ba);
    k_xtilde<<<(MM * NN / 4) / 256, 256>>>(X, out_xt);
    k_gemm<<<dim3(FH / 128, MM / 128), 256>>>(out_xt, Wl, bl);
    k_lstm<<<128, 512, SMEM_BYTES>>>(X, Ul, out_enc);
}

// round 6
// speedup vs baseline: 1.7959x; 1.7959x over previous
#include <cuda_runtime.h>
#include <cuda_bf16.h>
#include <cooperative_groups.h>
#include <math.h>

namespace cg = cooperative_groups;

// Fixed problem dims
#define BB   128
#define TT   255
#define NN   256
#define HH   256
#define FH   1024
#define MM   (BB*TT)          // 32640

// Static device scratch (no allocations allowed)
__device__ float g_alpha[BB * NN];
__device__ float g_P[(size_t)MM * FH];   // 133.7 MB

// ---------------------------------------------------------------------------
// helpers
// ---------------------------------------------------------------------------
__device__ __forceinline__ void ffma2(unsigned long long& d,
                                      unsigned long long a,
                                      unsigned long long b) {
    asm("fma.rn.f32x2 %0, %1, %2, %0;" : "+l"(d) : "l"(a), "l"(b));
}
__device__ __forceinline__ float pairsum(unsigned long long v) {
    float lo, hi;
    asm("mov.b64 {%0,%1}, %2;" : "=f"(lo), "=f"(hi) : "l"(v));
    return lo + hi;
}
__device__ __forceinline__ unsigned long long pack2(float a) {
    unsigned long long d;
    asm("mov.b64 %0, {%1,%1};" : "=l"(d) : "f"(a));
    return d;
}
__device__ __forceinline__ void unpack2(unsigned long long v, float& lo, float& hi) {
    asm("mov.b64 {%0,%1}, %2;" : "=f"(lo), "=f"(hi) : "l"(v));
}
__device__ __forceinline__ float sigf(float x) {
    return __fdividef(1.0f, 1.0f + __expf(-x));
}
__device__ __forceinline__ float tanh_fast(float x) {
    float e = __expf(-2.0f * x);
    return __fdividef(1.0f - e, 1.0f + e);
}

// ---------------------------------------------------------------------------
// K1: alpha[b,n] = softmax_n( b_attn + sum_t X[b,t,n] * Wa[2H+t] )
// (h/c logit terms are constant over n -> vanish under softmax)
// ---------------------------------------------------------------------------
__global__ __launch_bounds__(256) void k_alpha(const float* __restrict__ X,
                                               const float* __restrict__ Wa,
                                               const float* __restrict__ ba) {
    __shared__ float was[TT];
    __shared__ float red[256];
    const int b = blockIdx.x, n = threadIdx.x;
    if (n < TT) was[n] = Wa[2 * HH + n];
    __syncthreads();

    const float* xb = X + (size_t)b * TT * NN + n;
    float acc = ba[0];
#pragma unroll 5
    for (int t = 0; t < TT; ++t) acc = fmaf(xb[(size_t)t * NN], was[t], acc);

    red[n] = acc; __syncthreads();
    for (int s = 128; s > 0; s >>= 1) {
        if (n < s) red[n] = fmaxf(red[n], red[n + s]);
        __syncthreads();
    }
    const float mx = red[0]; __syncthreads();
    const float e = expf(acc - mx);
    red[n] = e; __syncthreads();
    for (int s = 128; s > 0; s >>= 1) {
        if (n < s) red[n] += red[n + s];
        __syncthreads();
    }
    g_alpha[b * NN + n] = e / red[0];
}

// ---------------------------------------------------------------------------
// K2: X_tilde = alpha * X  ->  d_out[0 : MM*NN)
// ---------------------------------------------------------------------------
__global__ __launch_bounds__(256) void k_xtilde(const float* __restrict__ X,
                                                float* __restrict__ out) {
    const int idx = blockIdx.x * 256 + threadIdx.x;          // < MM*NN/4
    const float4 x = ((const float4*)X)[idx];
    const int b   = idx / (TT * NN / 4);
    const int rem = idx - b * (TT * NN / 4);
    const int n4  = rem & (NN / 4 - 1);
    const float4 a = ((const float4*)g_alpha)[b * (NN / 4) + n4];
    float4 o;
    o.x = x.x * a.x; o.y = x.y * a.y; o.z = x.z * a.z; o.w = x.w * a.w;
    ((float4*)out)[idx] = o;
}

// ---------------------------------------------------------------------------
// K3: P = X_tilde @ W_lstm + b_lstm   (M=32640, Ncols=1024, K=256) fp32
// 128x128 tile, 256 threads, 8x8 microtile; inner product in fma.rn.f32x2.
// ---------------------------------------------------------------------------
__global__ __launch_bounds__(256) void k_gemm(const float* __restrict__ A,
                                              const float* __restrict__ W,
                                              const float* __restrict__ bias) {
    __shared__ float As[16 * 132];
    __shared__ float Bs[16 * 132];
    const int tx = threadIdx.x & 15;
    const int ty = threadIdx.x >> 4;
    const int m0 = blockIdx.y * 128;
    const int c0 = blockIdx.x * 128;

    unsigned long long acc2[8][4];
#pragma unroll
    for (int i = 0; i < 8; ++i)
#pragma unroll
        for (int j = 0; j < 4; ++j) acc2[i][j] = 0ull;

    for (int kk0 = 0; kk0 < 256; kk0 += 16) {
#pragma unroll
        for (int i = 0; i < 2; ++i) {               // A tile (transposed)
            const int id = threadIdx.x + 256 * i;
            const int q = id & 3, row = id >> 2;
            const float4 v = *(const float4*)(A + (size_t)(m0 + row) * 256 + kk0 + 4 * q);
            As[(4 * q + 0) * 132 + row] = v.x;
            As[(4 * q + 1) * 132 + row] = v.y;
            As[(4 * q + 2) * 132 + row] = v.z;
            As[(4 * q + 3) * 132 + row] = v.w;
        }
#pragma unroll
        for (int i = 0; i < 2; ++i) {               // B tile
            const int id = threadIdx.x + 256 * i;
            const int c4 = id & 31, k = id >> 5;
            *(float4*)(Bs + k * 132 + 4 * c4) =
                *(const float4*)(W + (size_t)(kk0 + k) * 1024 + c0 + 4 * c4);
        }
        __syncthreads();
#pragma unroll
        for (int kk = 0; kk < 16; ++kk) {
            const float4 a0 = *(const float4*)(As + kk * 132 + 4 * ty);
            const float4 a1 = *(const float4*)(As + kk * 132 + 64 + 4 * ty);
            const ulonglong2 bq0 = *(const ulonglong2*)(Bs + kk * 132 + 4 * tx);
            const ulonglong2 bq1 = *(const ulonglong2*)(Bs + kk * 132 + 64 + 4 * tx);
            const float av[8] = {a0.x, a0.y, a0.z, a0.w, a1.x, a1.y, a1.z, a1.w};
#pragma unroll
            for (int i = 0; i < 8; ++i) {
                const unsigned long long ad = pack2(av[i]);
                ffma2(acc2[i][0], ad, bq0.x);
                ffma2(acc2[i][1], ad, bq0.y);
                ffma2(acc2[i][2], ad, bq1.x);
                ffma2(acc2[i][3], ad, bq1.y);
            }
        }
        __syncthreads();
    }
#pragma unroll
    for (int i = 0; i < 8; ++i) {
        const int row = (i < 4) ? (4 * ty + i) : (64 + 4 * ty + (i - 4));
        float* p = g_P + (size_t)(m0 + row) * 1024 + c0;
        float4 o0, o1;
        float lo, hi;
        unpack2(acc2[i][0], lo, hi);
        o0.x = lo + bias[c0 + 4 * tx + 0];
        o0.y = hi + bias[c0 + 4 * tx + 1];
        unpack2(acc2[i][1], lo, hi);
        o0.z = lo + bias[c0 + 4 * tx + 2];
        o0.w = hi + bias[c0 + 4 * tx + 3];
        unpack2(acc2[i][2], lo, hi);
        o1.x = lo + bias[c0 + 64 + 4 * tx + 0];
        o1.y = hi + bias[c0 + 64 + 4 * tx + 1];
        unpack2(acc2[i][3], lo, hi);
        o1.z = lo + bias[c0 + 64 + 4 * tx + 2];
        o1.w = hi + bias[c0 + 64 + 4 * tx + 3];
        *(float4*)(p + 4 * tx) = o0;
        *(float4*)(p + 64 + 4 * tx) = o1;
    }
}

// ---------------------------------------------------------------------------
// K4 v3: LSTM recurrence, register-tiled to cut smem crossbar traffic 3.3x.
// 16 clusters x 8 CTAs; cluster owns 8 batches; CTA rank owns 32 hidden units
// (128 gate cols). 256 threads.
// Thread tile: 4 batches x (2 units x 4 gates) = 32 accumulators over a
// strided 1/8 k-slice (k = m*32 + ks*4, m=0..7). lane = sub*8 + ks.
// k-reduction via 3x shfl.xor (intra-warp, no syncthreads). After reduction
// lane ks owns one (batch,unit): c in register, gates colocated.
// U slice resident in smem; FFMA2 packed along k; P prefetched one step ahead;
// h broadcast via DSMEM stores; ONE cluster.sync per step.
// ---------------------------------------------------------------------------
#define PITCH 260
#define UT_FLOATS (128 * PITCH)            // 33280 floats (130 KB)
#define HB_STRIDE (8 * PITCH)              // 2080 floats per h buffer
#define SMEM_FLOATS (UT_FLOATS + 2 * HB_STRIDE)
#define SMEM_BYTES  (SMEM_FLOATS * 4)      // 149,760 B

__global__ __launch_bounds__(256, 1) __cluster_dims__(8, 1, 1)
void k_lstm(const float* __restrict__ X, const float* __restrict__ U,
            float* __restrict__ out_enc) {
    extern __shared__ float sm[];
    float* Ut = sm;                        // [128 gate-cols][k, pitch 260]
    float* hb = sm + UT_FLOATS;            // 2 x [8 batches][pitch 260]

    cg::cluster_group cl = cg::this_cluster();
    const int rank = (int)cl.block_rank();           // 0..7
    const int b0   = (blockIdx.x >> 3) * 8;
    const int tid  = threadIdx.x;
    const int w    = tid >> 5;
    const int lane = tid & 31;
    const int sub  = lane >> 3;                      // 0..3
    const int ks   = lane & 7;                       // k-slice 0..7
    const int tb   = w & 1;                          // batch group (4 batches)
    const int tu   = (w >> 1) * 4 + sub;             // unit-pair index 0..15

    // This lane's owned output cell (after reduction):
    const int bi_own = ks & 3;
    const int d_own  = ks >> 2;
    const int bb     = tb * 4 + bi_own;              // batch 0..7
    const int uu     = tu * 2 + d_own;               // unit 0..31
    const int jglob  = rank * 32 + uu;

    // Load U slice: Ut[(g*32+jr)*PITCH + k] = U[k*1024 + g*256 + rank*32 + jr]
    for (int idx = tid; idx < 128 * 256; idx += 256) {
        const int k = idx >> 7;
        const int cr = idx & 127;
        const int g = cr >> 5, jr = cr & 31;
        Ut[cr * PITCH + k] = U[(size_t)k * 1024 + g * 256 + rank * 32 + jr];
    }
    // h0 = c0 = X[b,0,0] broadcast across hidden; fill buffer 0 locally
    for (int idx = tid; idx < 8 * 256; idx += 256) {
        const int b = idx >> 8, k = idx & 255;
        hb[b * PITCH + k] = X[(size_t)(b0 + b) * TT * NN];
    }
    float c = X[(size_t)(b0 + bb) * TT * NN];
    cl.sync();

    // U pointers for this thread's 8 gate-cols: cr = g*32 + tu*2 + d
    const ulonglong2* Up[8];
#pragma unroll
    for (int g = 0; g < 4; ++g)
#pragma unroll
        for (int d = 0; d < 2; ++d)
            Up[g * 2 + d] = (const ulonglong2*)(Ut + (g * 32 + tu * 2 + d) * PITCH + ks * 4);

    const float* Pb = g_P + ((size_t)(b0 + bb) * TT) * 1024 + jglob;
    float* Ob = out_enc + ((size_t)(b0 + bb) * TT) * HH + jglob;

    float pi = Pb[0], pf = Pb[256], pg = Pb[512], po = Pb[768];

    for (int t = 0; t < TT; ++t) {
        const int cb = t & 1;
        // prefetch next-step P into registers (hidden behind FMA loop)
        float npi = 0.f, npf = 0.f, npg = 0.f, npo = 0.f;
        if (t + 1 < TT) {
            const float* pr = Pb + (size_t)(t + 1) * 1024;
            npi = pr[0]; npf = pr[256]; npg = pr[512]; npo = pr[768];
        }

        const float* hcur = hb + cb * HB_STRIDE;
        unsigned long long acc2[32];
#pragma unroll
        for (int i = 0; i < 32; ++i) acc2[i] = 0ull;

#pragma unroll
        for (int m = 0; m < 8; ++m) {
            ulonglong2 hv[4];
#pragma unroll
            for (int bi = 0; bi < 4; ++bi)
                hv[bi] = *(const ulonglong2*)(hcur + (tb * 4 + bi) * PITCH + ks * 4 + m * 32);
#pragma unroll
            for (int gd = 0; gd < 8; ++gd) {
                const ulonglong2 uv = Up[gd][m * 8];   // +m*128B
                const int g = gd >> 1, d = gd & 1;
#pragma unroll
                for (int bi = 0; bi < 4; ++bi) {
                    const int a = (bi * 2 + d) * 4 + g;
                    ffma2(acc2[a], hv[bi].x, uv.x);
                    ffma2(acc2[a], hv[bi].y, uv.y);
                }
            }
        }

        float red[32];
#pragma unroll
        for (int i = 0; i < 32; ++i) red[i] = pairsum(acc2[i]);
#pragma unroll
        for (int i = 0; i < 32; ++i) {
            red[i] += __shfl_xor_sync(0xffffffffu, red[i], 1);
            red[i] += __shfl_xor_sync(0xffffffffu, red[i], 2);
            red[i] += __shfl_xor_sync(0xffffffffu, red[i], 4);
        }

        const int base = (bi_own * 2 + d_own) * 4;
        const float gi = sigf(pi + red[base + 0]);
        const float gf = sigf(pf + red[base + 1]);
        const float gg = tanh_fast(pg + red[base + 2]);
        const float go = sigf(po + red[base + 3]);
        c = gf * c + gi * gg;
        const float h = go * tanh_fast(c);

        Ob[(size_t)t * HH] = h;

        if (t + 1 < TT) {
            float* hn = hb + (1 - cb) * HB_STRIDE;
            const int moff = bb * PITCH + jglob;
#pragma unroll
            for (int r2 = 0; r2 < 8; ++r2) {
                float* dst = cl.map_shared_rank(hn, r2);
                dst[moff] = h;
            }
        }
        pi = npi; pf = npf; pg = npg; po = npo;
        cl.sync();
    }
}

// ---------------------------------------------------------------------------
extern "C" void kernel_launch(void* const* d_in, const int* in_sizes, int n_in,
                              void* d_out, int out_size) {
    const float* X  = (const float*)d_in[0];
    const float* Wa = (const float*)d_in[1];
    const float* ba = (const float*)d_in[2];
    const float* Wl = (const float*)d_in[3];
    const float* Ul = (const float*)d_in[4];
    const float* bl = (const float*)d_in[5];
    float* out = (float*)d_out;
    float* out_xt  = out;                          // (B,Tm1,N)
    float* out_enc = out + (size_t)MM * NN;        // (B,Tm1,H)

    cudaFuncSetAttribute(k_lstm, cudaFuncAttributeMaxDynamicSharedMemorySize,
                         SMEM_BYTES);

    k_alpha<<<BB, 256>>>(X, Wa, ba);
    k_xtilde<<<(MM * NN / 4) / 256, 256>>>(X, out_xt);
    k_gemm<<<dim3(FH / 128, MM / 128), 256>>>(out_xt, Wl, bl);
    k_lstm<<<128, 256, SMEM_BYTES>>>(X, Ul, out_enc);
}

// round 8
// speedup vs baseline: 2.0306x; 1.1307x over previous
#include <cuda_runtime.h>
#include <cuda_bf16.h>
#include <cooperative_groups.h>
#include <math.h>

namespace cg = cooperative_groups;

// Fixed problem dims
#define BB   128
#define TT   255
#define NN   256
#define HH   256
#define FH   1024
#define MM   (BB*TT)          // 32640

// Static device scratch (no allocations allowed)
__device__ float g_alpha[BB * NN];
__device__ float g_P[(size_t)MM * FH];   // 133.7 MB

// ---------------------------------------------------------------------------
// helpers
// ---------------------------------------------------------------------------
__device__ __forceinline__ void ffma2(unsigned long long& d,
                                      unsigned long long a,
                                      unsigned long long b) {
    asm("fma.rn.f32x2 %0, %1, %2, %0;" : "+l"(d) : "l"(a), "l"(b));
}
__device__ __forceinline__ float pairsum(unsigned long long v) {
    float lo, hi;
    asm("mov.b64 {%0,%1}, %2;" : "=f"(lo), "=f"(hi) : "l"(v));
    return lo + hi;
}
__device__ __forceinline__ unsigned long long pack2(float a) {
    unsigned long long d;
    asm("mov.b64 %0, {%1,%1};" : "=l"(d) : "f"(a));
    return d;
}
__device__ __forceinline__ void unpack2(unsigned long long v, float& lo, float& hi) {
    asm("mov.b64 {%0,%1}, %2;" : "=f"(lo), "=f"(hi) : "l"(v));
}
__device__ __forceinline__ float sigf(float x) {
    return __fdividef(1.0f, 1.0f + __expf(-x));
}
__device__ __forceinline__ float tanh_fast(float x) {
    float e = __expf(-2.0f * x);
    return __fdividef(1.0f - e, 1.0f + e);
}

// ---------------------------------------------------------------------------
// K1: alpha[b,n] = softmax_n( b_attn + sum_t X[b,t,n] * Wa[2H+t] )
// (h/c logit terms are constant over n -> vanish under softmax)
// ---------------------------------------------------------------------------
__global__ __launch_bounds__(256) void k_alpha(const float* __restrict__ X,
                                               const float* __restrict__ Wa,
                                               const float* __restrict__ ba) {
    __shared__ float was[TT];
    __shared__ float red[256];
    const int b = blockIdx.x, n = threadIdx.x;
    if (n < TT) was[n] = Wa[2 * HH + n];
    __syncthreads();

    const float* xb = X + (size_t)b * TT * NN + n;
    float acc = ba[0];
#pragma unroll 5
    for (int t = 0; t < TT; ++t) acc = fmaf(xb[(size_t)t * NN], was[t], acc);

    red[n] = acc; __syncthreads();
    for (int s = 128; s > 0; s >>= 1) {
        if (n < s) red[n] = fmaxf(red[n], red[n + s]);
        __syncthreads();
    }
    const float mx = red[0]; __syncthreads();
    const float e = expf(acc - mx);
    red[n] = e; __syncthreads();
    for (int s = 128; s > 0; s >>= 1) {
        if (n < s) red[n] += red[n + s];
        __syncthreads();
    }
    g_alpha[b * NN + n] = e / red[0];
}

// ---------------------------------------------------------------------------
// K2: X_tilde = alpha * X  ->  d_out[0 : MM*NN)
// ---------------------------------------------------------------------------
__global__ __launch_bounds__(256) void k_xtilde(const float* __restrict__ X,
                                                float* __restrict__ out) {
    const int idx = blockIdx.x * 256 + threadIdx.x;          // < MM*NN/4
    const float4 x = ((const float4*)X)[idx];
    const int b   = idx / (TT * NN / 4);
    const int rem = idx - b * (TT * NN / 4);
    const int n4  = rem & (NN / 4 - 1);
    const float4 a = ((const float4*)g_alpha)[b * (NN / 4) + n4];
    float4 o;
    o.x = x.x * a.x; o.y = x.y * a.y; o.z = x.z * a.z; o.w = x.w * a.w;
    ((float4*)out)[idx] = o;
}

// ---------------------------------------------------------------------------
// K3: P = X_tilde @ W_lstm + b_lstm   (M=32640, Ncols=1024, K=256) fp32
// 128x128 tile, 256 threads, 8x8 microtile; inner product in fma.rn.f32x2.
// ---------------------------------------------------------------------------
__global__ __launch_bounds__(256) void k_gemm(const float* __restrict__ A,
                                              const float* __restrict__ W,
                                              const float* __restrict__ bias) {
    __shared__ float As[16 * 132];
    __shared__ float Bs[16 * 132];
    const int tx = threadIdx.x & 15;
    const int ty = threadIdx.x >> 4;
    const int m0 = blockIdx.y * 128;
    const int c0 = blockIdx.x * 128;

    unsigned long long acc2[8][4];
#pragma unroll
    for (int i = 0; i < 8; ++i)
#pragma unroll
        for (int j = 0; j < 4; ++j) acc2[i][j] = 0ull;

    for (int kk0 = 0; kk0 < 256; kk0 += 16) {
#pragma unroll
        for (int i = 0; i < 2; ++i) {               // A tile (transposed)
            const int id = threadIdx.x + 256 * i;
            const int q = id & 3, row = id >> 2;
            const float4 v = *(const float4*)(A + (size_t)(m0 + row) * 256 + kk0 + 4 * q);
            As[(4 * q + 0) * 132 + row] = v.x;
            As[(4 * q + 1) * 132 + row] = v.y;
            As[(4 * q + 2) * 132 + row] = v.z;
            As[(4 * q + 3) * 132 + row] = v.w;
        }
#pragma unroll
        for (int i = 0; i < 2; ++i) {               // B tile
            const int id = threadIdx.x + 256 * i;
            const int c4 = id & 31, k = id >> 5;
            *(float4*)(Bs + k * 132 + 4 * c4) =
                *(const float4*)(W + (size_t)(kk0 + k) * 1024 + c0 + 4 * c4);
        }
        __syncthreads();
#pragma unroll
        for (int kk = 0; kk < 16; ++kk) {
            const float4 a0 = *(const float4*)(As + kk * 132 + 4 * ty);
            const float4 a1 = *(const float4*)(As + kk * 132 + 64 + 4 * ty);
            const ulonglong2 bq0 = *(const ulonglong2*)(Bs + kk * 132 + 4 * tx);
            const ulonglong2 bq1 = *(const ulonglong2*)(Bs + kk * 132 + 64 + 4 * tx);
            const float av[8] = {a0.x, a0.y, a0.z, a0.w, a1.x, a1.y, a1.z, a1.w};
#pragma unroll
            for (int i = 0; i < 8; ++i) {
                const unsigned long long ad = pack2(av[i]);
                ffma2(acc2[i][0], ad, bq0.x);
                ffma2(acc2[i][1], ad, bq0.y);
                ffma2(acc2[i][2], ad, bq1.x);
                ffma2(acc2[i][3], ad, bq1.y);
            }
        }
        __syncthreads();
    }
#pragma unroll
    for (int i = 0; i < 8; ++i) {
        const int row = (i < 4) ? (4 * ty + i) : (64 + 4 * ty + (i - 4));
        float* p = g_P + (size_t)(m0 + row) * 1024 + c0;
        float4 o0, o1;
        float lo, hi;
        unpack2(acc2[i][0], lo, hi);
        o0.x = lo + bias[c0 + 4 * tx + 0];
        o0.y = hi + bias[c0 + 4 * tx + 1];
        unpack2(acc2[i][1], lo, hi);
        o0.z = lo + bias[c0 + 4 * tx + 2];
        o0.w = hi + bias[c0 + 4 * tx + 3];
        unpack2(acc2[i][2], lo, hi);
        o1.x = lo + bias[c0 + 64 + 4 * tx + 0];
        o1.y = hi + bias[c0 + 64 + 4 * tx + 1];
        unpack2(acc2[i][3], lo, hi);
        o1.z = lo + bias[c0 + 64 + 4 * tx + 2];
        o1.w = hi + bias[c0 + 64 + 4 * tx + 3];
        *(float4*)(p + 4 * tx) = o0;
        *(float4*)(p + 64 + 4 * tx) = o1;
    }
}

// ---------------------------------------------------------------------------
// K4 v4: LSTM recurrence — U in REGISTERS, h loads warp-broadcast, no shfl.
// 16 clusters x 8 CTAs; cluster owns 8 batches; CTA rank owns 32 hidden units
// (128 gate cols). 256 threads.
// Compute role: tid = KH*128 + col. Thread holds U[col][KH-half of k] in 64
// packed f32x2 regs, accumulates 8 batch chains; h[b][k-chunk] loads are the
// SAME address warp-wide (broadcast LDS.128 ~1 crossbar cyc).
// Reduction: float4 stores to red smem + one __syncthreads.
// Owner role: tid = batch*32 + unit keeps c in a register, applies gates,
// writes out, DSMEM-broadcasts h; ONE cluster.sync per step.
// ---------------------------------------------------------------------------
#define PITCH 260
#define UT_FLOATS (128 * PITCH)            // staging for U slice (130 KB)
#define HB_OFF    UT_FLOATS
#define HB_STRIDE (8 * PITCH)              // 2080 floats per h buffer
#define RED_OFF   (HB_OFF + 2 * HB_STRIDE)
#define SMEM_FLOATS (RED_OFF + 2048)       // red: [2][128][8]
#define SMEM_BYTES  (SMEM_FLOATS * 4)      // 157,952 B

__global__ __launch_bounds__(256, 1) __cluster_dims__(8, 1, 1)
void k_lstm(const float* __restrict__ X, const float* __restrict__ U,
            float* __restrict__ out_enc) {
    extern __shared__ float sm[];
    float* Ut  = sm;                       // [128 gate-cols][k, pitch 260]
    float* hb  = sm + HB_OFF;              // 2 x [8 batches][pitch 260]
    float* redb = sm + RED_OFF;            // [2][128 cols][8 batches]

    cg::cluster_group cl = cg::this_cluster();
    const int rank = (int)cl.block_rank();           // 0..7
    const int b0   = (blockIdx.x >> 3) * 8;
    const int tid  = threadIdx.x;
    // compute role
    const int col  = tid & 127;                      // gate-col 0..127
    const int KH   = tid >> 7;                       // k half 0/1
    // owner role
    const int ob   = tid >> 5;                       // batch 0..7 (warp id)
    const int ou   = tid & 31;                       // unit 0..31 (lane)
    const int jglob = rank * 32 + ou;

    // Stage U slice: Ut[(g*32+jr)*PITCH + k] = U[k*1024 + g*256 + rank*32 + jr]
    for (int idx = tid; idx < 128 * 256; idx += 256) {
        const int k = idx >> 7;
        const int cr = idx & 127;
        const int g = cr >> 5, jr = cr & 31;
        Ut[cr * PITCH + k] = U[(size_t)k * 1024 + g * 256 + rank * 32 + jr];
    }
    // h0 = c0 = X[b,0,0]; fill buffer 0
    for (int idx = tid; idx < 8 * 256; idx += 256) {
        const int b = idx >> 8, k = idx & 255;
        hb[b * PITCH + k] = X[(size_t)(b0 + b) * TT * NN];
    }
    float c = X[(size_t)(b0 + ob) * TT * NN];
    __syncthreads();

    // Pull this thread's U row-half into registers: 64 f32x2 in 32 ulonglong2
    ulonglong2 u2[32];
    {
        const float* ub = Ut + col * PITCH + KH * 128;
#pragma unroll
        for (int i = 0; i < 32; ++i) u2[i] = *(const ulonglong2*)(ub + 4 * i);
    }
    cl.sync();

    const float* Pb = g_P + ((size_t)(b0 + ob) * TT) * 1024 + jglob;
    float* Ob = out_enc + ((size_t)(b0 + ob) * TT) * HH + jglob;
    float pi = Pb[0], pf = Pb[256], pg = Pb[512], po = Pb[768];

    for (int t = 0; t < TT; ++t) {
        const int cb = t & 1;
        // prefetch next-step P into registers (overlaps with FMA loop)
        float npi = 0.f, npf = 0.f, npg = 0.f, npo = 0.f;
        if (t + 1 < TT) {
            const float* pr = Pb + (size_t)(t + 1) * 1024;
            npi = pr[0]; npf = pr[256]; npg = pr[512]; npo = pr[768];
        }

        const float* hc = hb + cb * HB_STRIDE + KH * 128;
        unsigned long long acc[8];
#pragma unroll
        for (int b = 0; b < 8; ++b) acc[b] = 0ull;

#pragma unroll
        for (int ch = 0; ch < 32; ++ch) {
            const ulonglong2 uv = u2[ch];
#pragma unroll
            for (int b = 0; b < 8; ++b) {
                const ulonglong2 hv = *(const ulonglong2*)(hc + b * PITCH + 4 * ch);
                ffma2(acc[b], hv.x, uv.x);
                ffma2(acc[b], hv.y, uv.y);
            }
        }

        float4 r0, r1;
        r0.x = pairsum(acc[0]); r0.y = pairsum(acc[1]);
        r0.z = pairsum(acc[2]); r0.w = pairsum(acc[3]);
        r1.x = pairsum(acc[4]); r1.y = pairsum(acc[5]);
        r1.z = pairsum(acc[6]); r1.w = pairsum(acc[7]);
        float* rp = redb + (KH * 128 + col) * 8;
        *(float4*)rp = r0;
        *(float4*)(rp + 4) = r1;
        __syncthreads();

        // owner phase: combine k halves, 4 gates
        const float* rq = redb + ou * 8 + ob;
        const float si = rq[0]          + rq[128 * 8];
        const float sf = rq[32 * 8]     + rq[(128 + 32) * 8];
        const float sg = rq[64 * 8]     + rq[(128 + 64) * 8];
        const float so = rq[96 * 8]     + rq[(128 + 96) * 8];

        const float gi = sigf(pi + si);
        const float gf = sigf(pf + sf);
        const float gg = tanh_fast(pg + sg);
        const float go = sigf(po + so);
        c = gf * c + gi * gg;
        const float h = go * tanh_fast(c);

        Ob[(size_t)t * HH] = h;

        if (t + 1 < TT) {
            float* hn = hb + (1 - cb) * HB_STRIDE;
            const int moff = ob * PITCH + jglob;
#pragma unroll
            for (int r2 = 0; r2 < 8; ++r2) {
                float* dst = cl.map_shared_rank(hn, r2);
                dst[moff] = h;
            }
        }
        pi = npi; pf = npf; pg = npg; po = npo;
        if (t + 1 < TT) cl.sync();
    }
}

// ---------------------------------------------------------------------------
extern "C" void kernel_launch(void* const* d_in, const int* in_sizes, int n_in,
                              void* d_out, int out_size) {
    const float* X  = (const float*)d_in[0];
    const float* Wa = (const float*)d_in[1];
    const float* ba = (const float*)d_in[2];
    const float* Wl = (const float*)d_in[3];
    const float* Ul = (const float*)d_in[4];
    const float* bl = (const float*)d_in[5];
    float* out = (float*)d_out;
    float* out_xt  = out;                          // (B,Tm1,N)
    float* out_enc = out + (size_t)MM * NN;        // (B,Tm1,H)

    cudaFuncSetAttribute(k_lstm, cudaFuncAttributeMaxDynamicSharedMemorySize,
                         SMEM_BYTES);

    k_alpha<<<BB, 256>>>(X, Wa, ba);
    k_xtilde<<<(MM * NN / 4) / 256, 256>>>(X, out_xt);
    k_gemm<<<dim3(FH / 128, MM / 128), 256>>>(out_xt, Wl, bl);
    k_lstm<<<128, 256, SMEM_BYTES>>>(X, Ul, out_enc);
}

// round 9
// speedup vs baseline: 2.2187x; 1.0926x over previous
#include <cuda_runtime.h>
#include <cuda_bf16.h>
#include <cooperative_groups.h>
#include <math.h>

namespace cg = cooperative_groups;

// Fixed problem dims
#define BB   128
#define TT   255
#define NN   256
#define HH   256
#define FH   1024
#define MM   (BB*TT)          // 32640

// Static device scratch (no allocations allowed)
__device__ float g_alpha[BB * NN];
__device__ float g_P[(size_t)MM * FH];   // 133.7 MB

// ---------------------------------------------------------------------------
// helpers
// ---------------------------------------------------------------------------
__device__ __forceinline__ uint32_t smem_u32(const void* p) {
    uint32_t a;
    asm("{ .reg .u64 t; cvta.to.shared.u64 t, %1; cvt.u32.u64 %0, t; }"
        : "=r"(a) : "l"(p));
    return a;
}
__device__ __forceinline__ uint32_t mapa_u32(uint32_t addr, uint32_t rank) {
    uint32_t r;
    asm("mapa.shared::cluster.u32 %0, %1, %2;" : "=r"(r) : "r"(addr), "r"(rank));
    return r;
}
__device__ __forceinline__ void ffma2(unsigned long long& d,
                                      unsigned long long a,
                                      unsigned long long b) {
    asm("fma.rn.f32x2 %0, %1, %2, %0;" : "+l"(d) : "l"(a), "l"(b));
}
__device__ __forceinline__ float pairsum(unsigned long long v) {
    float lo, hi;
    asm("mov.b64 {%0,%1}, %2;" : "=f"(lo), "=f"(hi) : "l"(v));
    return lo + hi;
}
__device__ __forceinline__ unsigned long long pack2(float a) {
    unsigned long long d;
    asm("mov.b64 %0, {%1,%1};" : "=l"(d) : "f"(a));
    return d;
}
__device__ __forceinline__ void unpack2(unsigned long long v, float& lo, float& hi) {
    asm("mov.b64 {%0,%1}, %2;" : "=f"(lo), "=f"(hi) : "l"(v));
}
__device__ __forceinline__ void mbar_init(uint32_t mbar, uint32_t count) {
    asm volatile("mbarrier.init.shared.b64 [%0], %1;" :: "r"(mbar), "r"(count)
                 : "memory");
}
__device__ __forceinline__ void mbar_arm_tx(uint32_t mbar, uint32_t tx) {
    asm volatile("mbarrier.arrive.expect_tx.shared.b64 _, [%0], %1;"
                 :: "r"(mbar), "r"(tx) : "memory");
}
__device__ __forceinline__ void mbar_wait_acq(uint32_t mbar, uint32_t parity) {
    uint32_t done;
    asm volatile(
        "{\n\t.reg .pred P;\n\t"
        "mbarrier.try_wait.parity.acquire.cluster.shared::cta.b64 P, [%1], %2;\n\t"
        "selp.b32 %0, 1, 0, P;\n\t}"
        : "=r"(done) : "r"(mbar), "r"(parity) : "memory");
    while (!done) {
        asm volatile(
            "{\n\t.reg .pred P;\n\t"
            "mbarrier.try_wait.parity.acquire.cluster.shared::cta.b64 P, [%1], %2, 0x989680;\n\t"
            "selp.b32 %0, 1, 0, P;\n\t}"
            : "=r"(done) : "r"(mbar), "r"(parity) : "memory");
    }
}
__device__ __forceinline__ void st_async_f32(uint32_t raddr, float v,
                                             uint32_t rmbar) {
    asm volatile(
        "st.async.shared::cluster.mbarrier::complete_tx::bytes.b32 [%0], %1, [%2];"
        :: "r"(raddr), "r"(__float_as_uint(v)), "r"(rmbar) : "memory");
}
__device__ __forceinline__ float sigf(float x) {
    return __fdividef(1.0f, 1.0f + __expf(-x));
}
__device__ __forceinline__ float tanh_fast(float x) {
    float e = __expf(-2.0f * x);
    return __fdividef(1.0f - e, 1.0f + e);
}

// ---------------------------------------------------------------------------
// K1: alpha[b,n] = softmax_n( b_attn + sum_t X[b,t,n] * Wa[2H+t] )
// ---------------------------------------------------------------------------
__global__ __launch_bounds__(256) void k_alpha(const float* __restrict__ X,
                                               const float* __restrict__ Wa,
                                               const float* __restrict__ ba) {
    __shared__ float was[TT];
    __shared__ float red[256];
    const int b = blockIdx.x, n = threadIdx.x;
    if (n < TT) was[n] = Wa[2 * HH + n];
    __syncthreads();

    const float* xb = X + (size_t)b * TT * NN + n;
    float acc = ba[0];
#pragma unroll 5
    for (int t = 0; t < TT; ++t) acc = fmaf(xb[(size_t)t * NN], was[t], acc);

    red[n] = acc; __syncthreads();
    for (int s = 128; s > 0; s >>= 1) {
        if (n < s) red[n] = fmaxf(red[n], red[n + s]);
        __syncthreads();
    }
    const float mx = red[0]; __syncthreads();
    const float e = expf(acc - mx);
    red[n] = e; __syncthreads();
    for (int s = 128; s > 0; s >>= 1) {
        if (n < s) red[n] += red[n + s];
        __syncthreads();
    }
    g_alpha[b * NN + n] = e / red[0];
}

// ---------------------------------------------------------------------------
// K2: X_tilde = alpha * X  ->  d_out[0 : MM*NN)
// ---------------------------------------------------------------------------
__global__ __launch_bounds__(256) void k_xtilde(const float* __restrict__ X,
                                                float* __restrict__ out) {
    const int idx = blockIdx.x * 256 + threadIdx.x;          // < MM*NN/4
    const float4 x = ((const float4*)X)[idx];
    const int b   = idx / (TT * NN / 4);
    const int rem = idx - b * (TT * NN / 4);
    const int n4  = rem & (NN / 4 - 1);
    const float4 a = ((const float4*)g_alpha)[b * (NN / 4) + n4];
    float4 o;
    o.x = x.x * a.x; o.y = x.y * a.y; o.z = x.z * a.z; o.w = x.w * a.w;
    ((float4*)out)[idx] = o;
}

// ---------------------------------------------------------------------------
// K3: P = X_tilde @ W_lstm + b_lstm   (M=32640, Ncols=1024, K=256) fp32
// ---------------------------------------------------------------------------
__global__ __launch_bounds__(256) void k_gemm(const float* __restrict__ A,
                                              const float* __restrict__ W,
                                              const float* __restrict__ bias) {
    __shared__ float As[16 * 132];
    __shared__ float Bs[16 * 132];
    const int tx = threadIdx.x & 15;
    const int ty = threadIdx.x >> 4;
    const int m0 = blockIdx.y * 128;
    const int c0 = blockIdx.x * 128;

    unsigned long long acc2[8][4];
#pragma unroll
    for (int i = 0; i < 8; ++i)
#pragma unroll
        for (int j = 0; j < 4; ++j) acc2[i][j] = 0ull;

    for (int kk0 = 0; kk0 < 256; kk0 += 16) {
#pragma unroll
        for (int i = 0; i < 2; ++i) {               // A tile (transposed)
            const int id = threadIdx.x + 256 * i;
            const int q = id & 3, row = id >> 2;
            const float4 v = *(const float4*)(A + (size_t)(m0 + row) * 256 + kk0 + 4 * q);
            As[(4 * q + 0) * 132 + row] = v.x;
            As[(4 * q + 1) * 132 + row] = v.y;
            As[(4 * q + 2) * 132 + row] = v.z;
            As[(4 * q + 3) * 132 + row] = v.w;
        }
#pragma unroll
        for (int i = 0; i < 2; ++i) {               // B tile
            const int id = threadIdx.x + 256 * i;
            const int c4 = id & 31, k = id >> 5;
            *(float4*)(Bs + k * 132 + 4 * c4) =
                *(const float4*)(W + (size_t)(kk0 + k) * 1024 + c0 + 4 * c4);
        }
        __syncthreads();
#pragma unroll
        for (int kk = 0; kk < 16; ++kk) {
            const float4 a0 = *(const float4*)(As + kk * 132 + 4 * ty);
            const float4 a1 = *(const float4*)(As + kk * 132 + 64 + 4 * ty);
            const ulonglong2 bq0 = *(const ulonglong2*)(Bs + kk * 132 + 4 * tx);
            const ulonglong2 bq1 = *(const ulonglong2*)(Bs + kk * 132 + 64 + 4 * tx);
            const float av[8] = {a0.x, a0.y, a0.z, a0.w, a1.x, a1.y, a1.z, a1.w};
#pragma unroll
            for (int i = 0; i < 8; ++i) {
                const unsigned long long ad = pack2(av[i]);
                ffma2(acc2[i][0], ad, bq0.x);
                ffma2(acc2[i][1], ad, bq0.y);
                ffma2(acc2[i][2], ad, bq1.x);
                ffma2(acc2[i][3], ad, bq1.y);
            }
        }
        __syncthreads();
    }
#pragma unroll
    for (int i = 0; i < 8; ++i) {
        const int row = (i < 4) ? (4 * ty + i) : (64 + 4 * ty + (i - 4));
        float* p = g_P + (size_t)(m0 + row) * 1024 + c0;
        float4 o0, o1;
        float lo, hi;
        unpack2(acc2[i][0], lo, hi);
        o0.x = lo + bias[c0 + 4 * tx + 0];
        o0.y = hi + bias[c0 + 4 * tx + 1];
        unpack2(acc2[i][1], lo, hi);
        o0.z = lo + bias[c0 + 4 * tx + 2];
        o0.w = hi + bias[c0 + 4 * tx + 3];
        unpack2(acc2[i][2], lo, hi);
        o1.x = lo + bias[c0 + 64 + 4 * tx + 0];
        o1.y = hi + bias[c0 + 64 + 4 * tx + 1];
        unpack2(acc2[i][3], lo, hi);
        o1.z = lo + bias[c0 + 64 + 4 * tx + 2];
        o1.w = hi + bias[c0 + 64 + 4 * tx + 3];
        *(float4*)(p + 4 * tx) = o0;
        *(float4*)(p + 64 + 4 * tx) = o1;
    }
}

// ---------------------------------------------------------------------------
// K4 v5: LSTM recurrence — 512 threads (4-way k-split), U in registers,
// broadcast h loads, h exchange via st.async + mbarrier (NO cluster.sync
// in the loop).
// Compute role (all 512): tid = KQ*128 + col; thread holds U[col][KQ-quarter]
// in 32 packed-f32x2 regs, accumulates 8 batch chains, stores partials to
// redA/redB (float4, conflict-free).
// Owner role (tid<256): tid = ob*32 + ou keeps c in a register, applies
// gates, writes out_enc, pushes h to all 8 CTAs via st.async with tx-counted
// mbarrier completion.
// ---------------------------------------------------------------------------
#define PITCH 260
#define UT_FLOATS (128 * PITCH)              // 33280 (staging, 130 KB)
#define HB_OFF    UT_FLOATS
#define HB_STRIDE (8 * PITCH)                // 2080 floats per h buffer
#define REDA_OFF  (HB_OFF + 2 * HB_STRIDE)   // 37440 (float4[512])
#define REDB_OFF  (REDA_OFF + 2048)          // 39488 (float4[512])
#define MBAR_OFF  (REDB_OFF + 2048)          // 41536 (2 x u64)
#define SMEM_FLOATS (MBAR_OFF + 4)
#define SMEM_BYTES  (SMEM_FLOATS * 4)        // 166,160 B
#define TX_PER_STEP (8 * 256 * 4)            // 8192 B into each CTA per step

__global__ __launch_bounds__(512, 1) __cluster_dims__(8, 1, 1)
void k_lstm(const float* __restrict__ X, const float* __restrict__ U,
            float* __restrict__ out_enc) {
    extern __shared__ float sm[];
    float* Ut   = sm;                        // [128 gate-cols][k, pitch 260]
    float* hb   = sm + HB_OFF;               // 2 x [8 batches][pitch 260]
    float4* redA = (float4*)(sm + REDA_OFF); // [4 KQ][128 col] batches 0..3
    float4* redB = (float4*)(sm + REDB_OFF); // [4 KQ][128 col] batches 4..7

    cg::cluster_group cl = cg::this_cluster();
    const int rank = (int)cl.block_rank();           // 0..7
    const int b0   = (blockIdx.x >> 3) * 8;
    const int tid  = threadIdx.x;
    // compute role
    const int col  = tid & 127;                      // gate-col 0..127
    const int KQ   = tid >> 7;                       // k quarter 0..3
    // owner role (tid < 256)
    const int ob   = tid >> 5;                       // batch 0..7
    const int ou   = tid & 31;                       // unit 0..31
    const int jglob = rank * 32 + ou;

    const uint32_t smb = smem_u32(sm);
    const uint32_t mbar0 = smb + MBAR_OFF * 4;       // mbar[i] at +8*i

    // Stage U slice: Ut[(g*32+jr)*PITCH + k] = U[k*1024 + g*256 + rank*32 + jr]
    for (int idx = tid; idx < 128 * 256; idx += 512) {
        const int k = idx >> 7;
        const int cr = idx & 127;
        const int g = cr >> 5, jr = cr & 31;
        Ut[cr * PITCH + k] = U[(size_t)k * 1024 + g * 256 + rank * 32 + jr];
    }
    // h0 = c0 = X[b,0,0]; fill buffer 0 locally
    for (int idx = tid; idx < 8 * 256; idx += 512) {
        const int b = idx >> 8, k = idx & 255;
        hb[b * PITCH + k] = X[(size_t)(b0 + b) * TT * NN];
    }
    if (tid == 0) {
        mbar_init(mbar0 + 0, 1);
        mbar_init(mbar0 + 8, 1);
        mbar_arm_tx(mbar0 + 0, TX_PER_STEP);   // first waited at t=2
        mbar_arm_tx(mbar0 + 8, TX_PER_STEP);   // first waited at t=1
    }
    __syncthreads();

    // Pull this thread's U quarter into registers: 64 floats = 16 ulonglong2
    ulonglong2 u2[16];
    {
        const float* ub = Ut + col * PITCH + KQ * 64;
#pragma unroll
        for (int i = 0; i < 16; ++i) u2[i] = *(const ulonglong2*)(ub + 4 * i);
    }
    float c = (tid < 256) ? X[(size_t)(b0 + ob) * TT * NN] : 0.0f;
    cl.sync();   // mbarriers + buffer0 visible cluster-wide (once)

    const float* Pb = g_P + ((size_t)(b0 + ob) * TT) * 1024 + jglob;
    float* Ob = out_enc + ((size_t)(b0 + ob) * TT) * HH + jglob;
    float pi = 0.f, pf = 0.f, pg = 0.f, po = 0.f;
    if (tid < 256) { pi = Pb[0]; pf = Pb[256]; pg = Pb[512]; po = Pb[768]; }

    uint32_t ph0 = 0, ph1 = 0;

    for (int t = 0; t < TT; ++t) {
        const int cb = t & 1;
        // prefetch next-step P before the wait (DRAM latency overlaps barrier)
        float npi = 0.f, npf = 0.f, npg = 0.f, npo = 0.f;
        if (tid < 256 && t + 1 < TT) {
            const float* pr = Pb + (size_t)(t + 1) * 1024;
            npi = pr[0]; npf = pr[256]; npg = pr[512]; npo = pr[768];
        }
        if (t > 0) {
            const uint32_t mb = mbar0 + 8 * cb;
            if (cb) { mbar_wait_acq(mb, ph1); ph1 ^= 1; }
            else    { mbar_wait_acq(mb, ph0); ph0 ^= 1; }
            if (tid == 0 && t + 2 < TT) mbar_arm_tx(mb, TX_PER_STEP);
        }

        const float* hc = hb + cb * HB_STRIDE + KQ * 64;
        unsigned long long acc[8];
#pragma unroll
        for (int b = 0; b < 8; ++b) acc[b] = 0ull;

#pragma unroll
        for (int ch = 0; ch < 16; ++ch) {
            const ulonglong2 uv = u2[ch];
#pragma unroll
            for (int b = 0; b < 8; ++b) {
                const ulonglong2 hv = *(const ulonglong2*)(hc + b * PITCH + 4 * ch);
                ffma2(acc[b], hv.x, uv.x);
                ffma2(acc[b], hv.y, uv.y);
            }
        }

        float4 r0, r1;
        r0.x = pairsum(acc[0]); r0.y = pairsum(acc[1]);
        r0.z = pairsum(acc[2]); r0.w = pairsum(acc[3]);
        r1.x = pairsum(acc[4]); r1.y = pairsum(acc[5]);
        r1.z = pairsum(acc[6]); r1.w = pairsum(acc[7]);
        redA[KQ * 128 + col] = r0;
        redB[KQ * 128 + col] = r1;
        __syncthreads();

        if (tid < 256) {
            // owner phase: combine 4 k-quarter partials, component = ob
            const float* ra = (const float*)((ob < 4) ? redA : redB);
            const int comp = ob & 3;
            float si = 0.f, sf = 0.f, sg = 0.f, so = 0.f;
#pragma unroll
            for (int q = 0; q < 4; ++q) {
                const int base = q * 128 * 4;
                si += ra[base + (0  + ou) * 4 + comp];
                sf += ra[base + (32 + ou) * 4 + comp];
                sg += ra[base + (64 + ou) * 4 + comp];
                so += ra[base + (96 + ou) * 4 + comp];
            }
            const float gi = sigf(pi + si);
            const float gf = sigf(pf + sf);
            const float gg = tanh_fast(pg + sg);
            const float go = sigf(po + so);
            c = gf * c + gi * gg;
            const float h = go * tanh_fast(c);

            Ob[(size_t)t * HH] = h;

            if (t + 1 < TT) {
                const int nb = 1 - cb;
                const uint32_t laddr = smb +
                    (HB_OFF + nb * HB_STRIDE + ob * PITCH + jglob) * 4;
                const uint32_t lmbar = mbar0 + 8 * nb;
#pragma unroll
                for (int r2 = 0; r2 < 8; ++r2) {
                    const uint32_t ra2 = mapa_u32(laddr, (uint32_t)r2);
                    const uint32_t rm2 = mapa_u32(lmbar, (uint32_t)r2);
                    st_async_f32(ra2, h, rm2);
                }
            }
            pi = npi; pf = npf; pg = npg; po = npo;
        }
    }
    cl.sync();   // teardown safety
}

// ---------------------------------------------------------------------------
extern "C" void kernel_launch(void* const* d_in, const int* in_sizes, int n_in,
                              void* d_out, int out_size) {
    const float* X  = (const float*)d_in[0];
    const float* Wa = (const float*)d_in[1];
    const float* ba = (const float*)d_in[2];
    const float* Wl = (const float*)d_in[3];
    const float* Ul = (const float*)d_in[4];
    const float* bl = (const float*)d_in[5];
    float* out = (float*)d_out;
    float* out_xt  = out;                          // (B,Tm1,N)
    float* out_enc = out + (size_t)MM * NN;        // (B,Tm1,H)

    cudaFuncSetAttribute(k_lstm, cudaFuncAttributeMaxDynamicSharedMemorySize,
                         SMEM_BYTES);

    k_alpha<<<BB, 256>>>(X, Wa, ba);
    k_xtilde<<<(MM * NN / 4) / 256, 256>>>(X, out_xt);
    k_gemm<<<dim3(FH / 128, MM / 128), 256>>>(out_xt, Wl, bl);
    k_lstm<<<128, 512, SMEM_BYTES>>>(X, Ul, out_enc);
}